// round 1
// baseline (speedup 1.0000x reference)
#include <cuda_runtime.h>
#include <cuda_bf16.h>
#include <mma.h>

using namespace nvcuda;

// Problem constants
#define BATCH 4
#define SEQ 2048
#define EMB 2048
#define NH 16
#define DH 128
#define BH (BATCH * NH)          // 64
#define SD (SEQ * DH)            // 262144 per (b,h)
#define SS ((size_t)SEQ * SEQ)   // 4194304 per (b,h)

// Scratch (device globals: allocation-free rule)
__device__ float g_q[(size_t)BH * SD];
__device__ float g_k[(size_t)BH * SD];
__device__ float g_v[(size_t)BH * SD];
__device__ float g_scores[(size_t)BH * SS];   // reused in-place for softmax probs
__device__ float g_ctx[(size_t)BATCH * SEQ * EMB];

// ---------------------------------------------------------------------------
// Generic TF32 WMMA GEMM: C[M,N] = A[M,K] * B^T   (or A*B for MODE 2)
// Block tile 128x128, BK=32, 256 threads = 8 warps (4 row x 2 col),
// each warp: 32x64 via 2x4 m16n16k8 fragments, fp32 accumulate.
// MODE 0: QKV projection   A=x[8192,2048], B=W[2048,2048] (B^T), out scatter to g_q/g_k/g_v
// MODE 1: scores (batched) A=Q_bh[2048,128], B=K_bh (B^T), out=g_scores; skip upper-tri blocks
// MODE 2: ctx (batched)    A=P_bh[2048,2048], B=V_bh[2048,128] (row-major B), K truncated causally
// MODE 3: out projection   A=g_ctx[8192,2048], B=Wo (B^T), out=d_out
// ---------------------------------------------------------------------------
template<int MODE>
__global__ __launch_bounds__(256)
void gemm_tf32(const float* __restrict__ Aext,
               const float* __restrict__ Bext,
               float* __restrict__ Oext,
               int sel)
{
    constexpr bool BROW = (MODE == 2);   // B fragment row-major (P*V) vs col-major (A*B^T)

    const int tid = threadIdx.x;
    const int wid = tid >> 5;
    const int wr  = wid & 3;    // warp row: 32 rows each
    const int wc  = wid >> 2;   // warp col: 64 cols each
    const int m0  = blockIdx.y * 128;
    const int n0  = blockIdx.x * 128;
    const int z   = blockIdx.z;

    if (MODE == 1 && blockIdx.x > blockIdx.y) return;  // fully-masked causal block

    const float* A;  int lda;
    const float* Bm; int ldb;
    int Ktot;
    if (MODE == 0) { A = Aext;                     lda = EMB; Bm = Bext;                  ldb = EMB; Ktot = EMB; }
    else if (MODE == 1) { A = g_q + (size_t)z * SD; lda = DH;  Bm = g_k + (size_t)z * SD;  ldb = DH;  Ktot = DH; }
    else if (MODE == 2) { A = g_scores + (size_t)z * SS; lda = SEQ; Bm = g_v + (size_t)z * SD; ldb = DH; Ktot = m0 + 128; }
    else               { A = g_ctx;                lda = EMB; Bm = Bext;                  ldb = EMB; Ktot = EMB; }

    __shared__ float As[128 * 40];
    __shared__ float Bs[BROW ? 32 * 136 : 128 * 40];

    wmma::fragment<wmma::accumulator, 16, 16, 8, float> acc[2][4];
    #pragma unroll
    for (int i = 0; i < 2; i++)
        #pragma unroll
        for (int j = 0; j < 4; j++)
            wmma::fill_fragment(acc[i][j], 0.0f);

    for (int k0 = 0; k0 < Ktot; k0 += 32) {
        // load A tile [128 rows x 32 k], padded stride 40
        #pragma unroll
        for (int i = 0; i < 4; i++) {
            int idx = tid + i * 256;
            int r = idx >> 3, c = (idx & 7) * 4;
            *(float4*)(&As[r * 40 + c]) =
                *(const float4*)(&A[(size_t)(m0 + r) * lda + k0 + c]);
        }
        // load B tile
        if (!BROW) {
            // B^T: rows n of [N,K] matrix -> Bs[n][k] (col-major fragment view)
            #pragma unroll
            for (int i = 0; i < 4; i++) {
                int idx = tid + i * 256;
                int r = idx >> 3, c = (idx & 7) * 4;
                *(float4*)(&Bs[r * 40 + c]) =
                    *(const float4*)(&Bm[(size_t)(n0 + r) * ldb + k0 + c]);
            }
        } else {
            // row-major B: Bs[k][n], 32 x 128, padded stride 136
            #pragma unroll
            for (int i = 0; i < 4; i++) {
                int idx = tid + i * 256;
                int r = idx >> 5, c = (idx & 31) * 4;
                *(float4*)(&Bs[r * 136 + c]) =
                    *(const float4*)(&Bm[(size_t)(k0 + r) * ldb + n0 + c]);
            }
        }
        __syncthreads();

        #pragma unroll
        for (int ks = 0; ks < 4; ks++) {
            wmma::fragment<wmma::matrix_a, 16, 16, 8, wmma::precision::tf32, wmma::row_major> af[2];
            #pragma unroll
            for (int i = 0; i < 2; i++) {
                wmma::load_matrix_sync(af[i], &As[(wr * 32 + i * 16) * 40 + ks * 8], 40);
                #pragma unroll
                for (int t = 0; t < af[i].num_elements; t++)
                    af[i].x[t] = wmma::__float_to_tf32(af[i].x[t]);
            }
            if (!BROW) {
                #pragma unroll
                for (int j = 0; j < 4; j++) {
                    wmma::fragment<wmma::matrix_b, 16, 16, 8, wmma::precision::tf32, wmma::col_major> bf;
                    wmma::load_matrix_sync(bf, &Bs[(wc * 64 + j * 16) * 40 + ks * 8], 40);
                    #pragma unroll
                    for (int t = 0; t < bf.num_elements; t++)
                        bf.x[t] = wmma::__float_to_tf32(bf.x[t]);
                    #pragma unroll
                    for (int i = 0; i < 2; i++)
                        wmma::mma_sync(acc[i][j], af[i], bf, acc[i][j]);
                }
            } else {
                #pragma unroll
                for (int j = 0; j < 4; j++) {
                    wmma::fragment<wmma::matrix_b, 16, 16, 8, wmma::precision::tf32, wmma::row_major> bf;
                    wmma::load_matrix_sync(bf, &Bs[(ks * 8) * 136 + wc * 64 + j * 16], 136);
                    #pragma unroll
                    for (int t = 0; t < bf.num_elements; t++)
                        bf.x[t] = wmma::__float_to_tf32(bf.x[t]);
                    #pragma unroll
                    for (int i = 0; i < 2; i++)
                        wmma::mma_sync(acc[i][j], af[i], bf, acc[i][j]);
                }
            }
        }
        __syncthreads();
    }

    // Epilogue: resolve output pointer + leading dim per mode
    float* outp; int ldo;
    if (MODE == 0) {
        int b = m0 >> 11;                       // 2048 rows per batch
        float* base = (sel == 0 ? g_q : sel == 1 ? g_k : g_v)
                      + ((size_t)(b * NH + blockIdx.x)) * SD;  // blockIdx.x == head (128-col tile)
        outp = base + (size_t)(m0 & (SEQ - 1)) * DH;
        ldo = DH;
    } else if (MODE == 1) {
        outp = g_scores + (size_t)z * SS + (size_t)m0 * SEQ + n0;
        ldo = SEQ;
    } else if (MODE == 2) {
        int b = z >> 4, h = z & 15;
        outp = g_ctx + (size_t)b * SEQ * EMB + (size_t)m0 * EMB + h * DH;
        ldo = EMB;
    } else {
        outp = Oext + (size_t)m0 * EMB + n0;
        ldo = EMB;
    }

    #pragma unroll
    for (int i = 0; i < 2; i++)
        #pragma unroll
        for (int j = 0; j < 4; j++)
            wmma::store_matrix_sync(outp + (size_t)(wr * 32 + i * 16) * ldo + wc * 64 + j * 16,
                                    acc[i][j], ldo, wmma::mem_row_major);
}

// ---------------------------------------------------------------------------
// Causal row softmax, in-place on g_scores. One 256-thread block per (q, bh).
// ---------------------------------------------------------------------------
__global__ __launch_bounds__(256)
void softmax_causal()
{
    const int q  = blockIdx.x;
    const int bh = blockIdx.y;
    float* row = g_scores + (size_t)bh * SS + (size_t)q * SEQ;
    const float inv = 0.08838834764831845f;   // 1/sqrt(128)
    const int n = q + 1;
    const int t = threadIdx.x;

    float vals[8];
    float m = -1e30f;
    #pragma unroll
    for (int i = 0; i < 8; i++) {
        int idx = t + i * 256;
        float v = (idx < n) ? row[idx] : -1e30f;
        vals[i] = v;
        m = fmaxf(m, v);
    }

    __shared__ float red[256];
    red[t] = m; __syncthreads();
    #pragma unroll
    for (int s = 128; s > 0; s >>= 1) {
        if (t < s) red[t] = fmaxf(red[t], red[t + s]);
        __syncthreads();
    }
    m = red[0];
    __syncthreads();

    float sum = 0.0f;
    #pragma unroll
    for (int i = 0; i < 8; i++) {
        int idx = t + i * 256;
        if (idx < n) {
            float p = __expf((vals[i] - m) * inv);
            vals[i] = p;
            sum += p;
        }
    }
    red[t] = sum; __syncthreads();
    #pragma unroll
    for (int s = 128; s > 0; s >>= 1) {
        if (t < s) red[t] += red[t + s];
        __syncthreads();
    }
    const float rs = 1.0f / red[0];

    #pragma unroll
    for (int i = 0; i < 8; i++) {
        int idx = t + i * 256;
        if (idx < SEQ) row[idx] = (idx < n) ? vals[i] * rs : 0.0f;
    }
}

__global__ void add_bias(float* __restrict__ out, const float* __restrict__ bo)
{
    size_t i = (size_t)blockIdx.x * blockDim.x + threadIdx.x;
    if (i < (size_t)BATCH * SEQ * EMB) out[i] += bo[i & (EMB - 1)];
}

extern "C" void kernel_launch(void* const* d_in, const int* in_sizes, int n_in,
                              void* d_out, int out_size)
{
    const float* x  = (const float*)d_in[0];
    const float* Wq = (const float*)d_in[1];
    const float* Wk = (const float*)d_in[2];
    const float* Wv = (const float*)d_in[3];
    const float* Wo = (const float*)d_in[4];
    const float* bo = (const float*)d_in[5];
    float* out = (float*)d_out;

    dim3 blk(256);

    // Q/K/V projections: M=8192, N=2048, K=2048
    gemm_tf32<0><<<dim3(16, 64, 1), blk>>>(x, Wq, nullptr, 0);
    gemm_tf32<0><<<dim3(16, 64, 1), blk>>>(x, Wk, nullptr, 1);
    gemm_tf32<0><<<dim3(16, 64, 1), blk>>>(x, Wv, nullptr, 2);

    // scores = Q K^T, batched over 64 (b,h); upper-tri blocks skipped
    gemm_tf32<1><<<dim3(16, 16, BH), blk>>>(nullptr, nullptr, nullptr, 0);

    // causal softmax (scale folded in), in place
    softmax_causal<<<dim3(SEQ, BH), blk>>>();

    // ctx = P V, batched; K-loop causally truncated
    gemm_tf32<2><<<dim3(1, 16, BH), blk>>>(nullptr, nullptr, nullptr, 0);

    // out = ctx Wo^T
    gemm_tf32<3><<<dim3(16, 64, 1), blk>>>(nullptr, Wo, out, 0);

    // + bias
    add_bias<<<(BATCH * SEQ * EMB + 511) / 512, 512>>>(out, bo);
}

// round 3
// speedup vs baseline: 1.7289x; 1.7289x over previous
#include <cuda_runtime.h>
#include <cstdint>
#include <mma.h>

using namespace nvcuda;

// ---------------- problem constants ----------------
#define BATCH 4
#define SEQ 2048
#define EMB 2048
#define NH 16
#define DH 128
#define BH (BATCH * NH)          // 64
#define SD (SEQ * DH)            // 262144
#define SS ((size_t)SEQ * SEQ)

// scratch (allocation-free rule)
__device__ float g_q[(size_t)BH * SD];
__device__ float g_k[(size_t)BH * SD];
__device__ float g_v[(size_t)BH * SD];
__device__ float g_scores[(size_t)BH * SS];
__device__ float g_ctx[(size_t)BATCH * SEQ * EMB];
__device__ float g_xt[(size_t)BATCH * SEQ * EMB];   // tf32-rounded x
__device__ float g_wt[4][(size_t)EMB * EMB];        // tf32-rounded Wq,Wk,Wv,Wo

__device__ __forceinline__ float rtf32(float x) {
    float y;
    asm("cvt.rna.tf32.f32 %0, %1;" : "=f"(y) : "f"(x));
    return y;
}
__device__ __forceinline__ uint32_t smem_u32(const void* p) {
    return (uint32_t)__cvta_generic_to_shared(p);
}
__device__ __forceinline__ void cp16(uint32_t s, const void* g) {
    asm volatile("cp.async.cg.shared.global [%0], [%1], 16;\n" :: "r"(s), "l"(g));
}

// ---------------------------------------------------------------------------
// TF32 WMMA GEMM with 3-stage cp.async pipeline.
// CTA tile 128x128, BK=32, 256 threads = 8 warps (4 row x 2 col),
// warp tile 32x64 (2x4 m16n16k8 accumulators). No conversions in mainloop
// (all operands pre-rounded to tf32).
// MODE 0: QKV proj   C = x_t * W_t^T, scatter to g_q/g_k/g_v per head (rounded)
// MODE 1: scores     C = Q K^T per (b,h); upper-tri blocks skipped
// MODE 2: ctx        C = P V per (b,h); K truncated causally (rounded store)
// MODE 3: out proj   C = ctx * Wo_t^T
// ---------------------------------------------------------------------------
#define BK 32
#define A_STRIDE 40
#define B_STRIDE 40
#define B2_STRIDE 136
#define A_BYTES (128 * A_STRIDE * 4)            // 20480
#define STAGE_BYTES (A_BYTES + 128 * B_STRIDE * 4)  // 40960
#define NSTAGE 3
#define SMEM_BYTES (NSTAGE * STAGE_BYTES)

template<int MODE>
__global__ __launch_bounds__(256)
void gemm_tc(const float* __restrict__ Aext, const float* __restrict__ Bext,
             float* __restrict__ Oext, int sel)
{
    if (MODE == 1 && blockIdx.x > blockIdx.y) return;   // fully-masked causal block

    extern __shared__ float dyn[];

    const int tid = threadIdx.x;
    const int wid = tid >> 5;
    const int wr  = wid & 3;
    const int wc  = wid >> 2;
    const int m0  = blockIdx.y * 128;
    const int n0  = blockIdx.x * 128;
    const int z   = blockIdx.z;

    const float* A;  int lda;
    const float* Bm; int ldb;
    int Ktot;
    if (MODE == 0)      { A = Aext;                      lda = EMB; Bm = Bext;                 ldb = EMB; Ktot = EMB; }
    else if (MODE == 1) { A = g_q + (size_t)z * SD;      lda = DH;  Bm = g_k + (size_t)z * SD; ldb = DH;  Ktot = DH; }
    else if (MODE == 2) { A = g_scores + (size_t)z * SS; lda = SEQ; Bm = g_v + (size_t)z * SD; ldb = DH;  Ktot = m0 + 128; }
    else                { A = g_ctx;                     lda = EMB; Bm = Bext;                 ldb = EMB; Ktot = EMB; }
    const int T = Ktot / BK;

    const uint32_t sbase = smem_u32(dyn);

    // ---- stage loader: issues cp.async for k-tile t into buffer buf ----
    auto load_stage = [&](int buf, int t) {
        const uint32_t sa = sbase + (uint32_t)buf * STAGE_BYTES;
        const uint32_t sb = sa + A_BYTES;
        const int k0 = t * BK;
        // A: 128 x 32, row stride 40 floats
        #pragma unroll
        for (int i = 0; i < 4; i++) {
            int id = tid + i * 256;
            int r = id >> 3, c = (id & 7) * 4;
            cp16(sa + (uint32_t)(r * A_STRIDE + c) * 4,
                 A + (size_t)(m0 + r) * lda + k0 + c);
        }
        if (MODE != 2) {
            // B rows are N-dim, K contiguous: 128 x 32, stride 40
            #pragma unroll
            for (int i = 0; i < 4; i++) {
                int id = tid + i * 256;
                int r = id >> 3, c = (id & 7) * 4;
                cp16(sb + (uint32_t)(r * B_STRIDE + c) * 4,
                     Bm + (size_t)(n0 + r) * ldb + k0 + c);
            }
        } else {
            // V row-major [K, 128]: Bs[k][n], 32 x 128, stride 136
            #pragma unroll
            for (int i = 0; i < 4; i++) {
                int id = tid + i * 256;
                int r = id >> 5, c = (id & 31) * 4;
                cp16(sb + (uint32_t)(r * B2_STRIDE + c) * 4,
                     Bm + (size_t)(k0 + r) * ldb + n0 + c);
            }
        }
        asm volatile("cp.async.commit_group;\n");
    };

    wmma::fragment<wmma::accumulator, 16, 16, 8, float> acc[2][4];
    #pragma unroll
    for (int i = 0; i < 2; i++)
        #pragma unroll
        for (int j = 0; j < 4; j++)
            wmma::fill_fragment(acc[i][j], 0.0f);

    // prologue: stages 0 and 1 in flight
    load_stage(0, 0);
    load_stage(1, 1);

    for (int t = 0; t < T; t++) {
        asm volatile("cp.async.wait_group 1;\n" ::: "memory");
        __syncthreads();

        // issue next stage (safe: all warps finished compute(t-1) on this buffer)
        if (t + 2 < T) load_stage((t + 2) % NSTAGE, t + 2);
        else asm volatile("cp.async.commit_group;\n");   // keep group count uniform

        const float* As = dyn + ((t % NSTAGE) * STAGE_BYTES) / 4;
        const float* Bs = As + A_BYTES / 4;

        #pragma unroll
        for (int ks = 0; ks < 4; ks++) {
            wmma::fragment<wmma::matrix_a, 16, 16, 8, wmma::precision::tf32, wmma::row_major> af[2];
            #pragma unroll
            for (int i = 0; i < 2; i++)
                wmma::load_matrix_sync(af[i], &As[(wr * 32 + i * 16) * A_STRIDE + ks * 8], A_STRIDE);
            if (MODE != 2) {
                #pragma unroll
                for (int j = 0; j < 4; j++) {
                    wmma::fragment<wmma::matrix_b, 16, 16, 8, wmma::precision::tf32, wmma::col_major> bf;
                    wmma::load_matrix_sync(bf, &Bs[(wc * 64 + j * 16) * B_STRIDE + ks * 8], B_STRIDE);
                    #pragma unroll
                    for (int i = 0; i < 2; i++)
                        wmma::mma_sync(acc[i][j], af[i], bf, acc[i][j]);
                }
            } else {
                #pragma unroll
                for (int j = 0; j < 4; j++) {
                    wmma::fragment<wmma::matrix_b, 16, 16, 8, wmma::precision::tf32, wmma::row_major> bf;
                    wmma::load_matrix_sync(bf, &Bs[(ks * 8) * B2_STRIDE + wc * 64 + j * 16], B2_STRIDE);
                    #pragma unroll
                    for (int i = 0; i < 2; i++)
                        wmma::mma_sync(acc[i][j], af[i], bf, acc[i][j]);
                }
            }
        }
    }

    // ---- epilogue ----
    float* outp; int ldo;
    bool do_round;
    if (MODE == 0) {
        int b = m0 >> 11;
        float* qkv = (sel == 0 ? g_q : sel == 1 ? g_k : g_v);
        outp = qkv + ((size_t)(b * NH + blockIdx.x)) * SD + (size_t)(m0 & (SEQ - 1)) * DH;
        ldo = DH;
        do_round = true;
    } else if (MODE == 1) {
        outp = g_scores + (size_t)z * SS + (size_t)m0 * SEQ + n0;
        ldo = SEQ;
        do_round = false;
    } else if (MODE == 2) {
        int b = z >> 4, h = z & 15;
        outp = g_ctx + (size_t)b * SEQ * EMB + (size_t)m0 * EMB + h * DH;
        ldo = EMB;
        do_round = true;
    } else {
        outp = Oext + (size_t)m0 * EMB + n0;
        ldo = EMB;
        do_round = false;
    }

    #pragma unroll
    for (int i = 0; i < 2; i++)
        #pragma unroll
        for (int j = 0; j < 4; j++) {
            if (do_round) {
                #pragma unroll
                for (int e = 0; e < acc[i][j].num_elements; e++)
                    acc[i][j].x[e] = rtf32(acc[i][j].x[e]);
            }
            wmma::store_matrix_sync(outp + (size_t)(wr * 32 + i * 16) * ldo + wc * 64 + j * 16,
                                    acc[i][j], ldo, wmma::mem_row_major);
        }
}

// ---------------------------------------------------------------------------
// causal row softmax, in place on g_scores; probs stored tf32-rounded
// ---------------------------------------------------------------------------
__global__ __launch_bounds__(256)
void softmax_causal()
{
    const int q  = blockIdx.x;
    const int bh = blockIdx.y;
    float* row = g_scores + (size_t)bh * SS + (size_t)q * SEQ;
    const float inv = 0.08838834764831845f;   // 1/sqrt(128)
    const int n = q + 1;
    const int t = threadIdx.x;

    float vals[8];
    float m = -1e30f;
    #pragma unroll
    for (int i = 0; i < 8; i++) {
        int idx = t + i * 256;
        float v = (idx < n) ? row[idx] : -1e30f;
        vals[i] = v;
        m = fmaxf(m, v);
    }
    __shared__ float red[256];
    red[t] = m; __syncthreads();
    #pragma unroll
    for (int s = 128; s > 0; s >>= 1) {
        if (t < s) red[t] = fmaxf(red[t], red[t + s]);
        __syncthreads();
    }
    m = red[0];
    __syncthreads();

    float sum = 0.0f;
    #pragma unroll
    for (int i = 0; i < 8; i++) {
        int idx = t + i * 256;
        if (idx < n) {
            float p = __expf((vals[i] - m) * inv);
            vals[i] = p;
            sum += p;
        }
    }
    red[t] = sum; __syncthreads();
    #pragma unroll
    for (int s = 128; s > 0; s >>= 1) {
        if (t < s) red[t] += red[t + s];
        __syncthreads();
    }
    const float rs = 1.0f / red[0];

    #pragma unroll
    for (int i = 0; i < 8; i++) {
        int idx = t + i * 256;
        if (idx < SEQ) row[idx] = (idx < n) ? rtf32(vals[i] * rs) : 0.0f;
    }
}

// elementwise tf32 rounding pre-pass (float4 grid-stride)
__global__ void round_pass(const float4* __restrict__ in, float4* __restrict__ out, int n4)
{
    int i = blockIdx.x * blockDim.x + threadIdx.x;
    if (i < n4) {
        float4 v = in[i];
        v.x = rtf32(v.x); v.y = rtf32(v.y); v.z = rtf32(v.z); v.w = rtf32(v.w);
        out[i] = v;
    }
}

__global__ void add_bias(float* __restrict__ out, const float* __restrict__ bo)
{
    size_t i = (size_t)blockIdx.x * blockDim.x + threadIdx.x;
    if (i < (size_t)BATCH * SEQ * EMB) out[i] += bo[i & (EMB - 1)];
}

extern "C" void kernel_launch(void* const* d_in, const int* in_sizes, int n_in,
                              void* d_out, int out_size)
{
    const float* x  = (const float*)d_in[0];
    const float* W[4] = {(const float*)d_in[1], (const float*)d_in[2],
                         (const float*)d_in[3], (const float*)d_in[4]};
    const float* bo = (const float*)d_in[5];
    float* out = (float*)d_out;

    cudaFuncSetAttribute(gemm_tc<0>, cudaFuncAttributeMaxDynamicSharedMemorySize, SMEM_BYTES);
    cudaFuncSetAttribute(gemm_tc<1>, cudaFuncAttributeMaxDynamicSharedMemorySize, SMEM_BYTES);
    cudaFuncSetAttribute(gemm_tc<2>, cudaFuncAttributeMaxDynamicSharedMemorySize, SMEM_BYTES);
    cudaFuncSetAttribute(gemm_tc<3>, cudaFuncAttributeMaxDynamicSharedMemorySize, SMEM_BYTES);

    // resolve device-global scratch addresses
    float *xt, *wt;
    cudaGetSymbolAddress((void**)&xt, g_xt);
    cudaGetSymbolAddress((void**)&wt, g_wt);

    dim3 blk(256);
    const int XN4 = BATCH * SEQ * EMB / 4;   // 4.19M float4
    const int WN4 = EMB * EMB / 4;

    // pre-round x and weights to tf32
    round_pass<<<(XN4 + 255) / 256, 256>>>((const float4*)x, (float4*)xt, XN4);
    for (int i = 0; i < 4; i++)
        round_pass<<<(WN4 + 255) / 256, 256>>>((const float4*)W[i],
                                               (float4*)(wt + (size_t)i * EMB * EMB), WN4);

    // QKV projections: M=8192, N=2048, K=2048
    gemm_tc<0><<<dim3(16, 64, 1), blk, SMEM_BYTES>>>(xt, wt + 0 * (size_t)EMB * EMB, nullptr, 0);
    gemm_tc<0><<<dim3(16, 64, 1), blk, SMEM_BYTES>>>(xt, wt + 1 * (size_t)EMB * EMB, nullptr, 1);
    gemm_tc<0><<<dim3(16, 64, 1), blk, SMEM_BYTES>>>(xt, wt + 2 * (size_t)EMB * EMB, nullptr, 2);

    // scores = Q K^T per (b,h); upper-tri blocks skipped
    gemm_tc<1><<<dim3(16, 16, BH), blk, SMEM_BYTES>>>(nullptr, nullptr, nullptr, 0);

    // causal softmax (scale folded in), in place, tf32-rounded probs
    softmax_causal<<<dim3(SEQ, BH), blk>>>();

    // ctx = P V per (b,h); K truncated causally
    gemm_tc<2><<<dim3(1, 16, BH), blk, SMEM_BYTES>>>(nullptr, nullptr, nullptr, 0);

    // out = ctx Wo^T
    gemm_tc<3><<<dim3(16, 64, 1), blk, SMEM_BYTES>>>(nullptr, wt + 3 * (size_t)EMB * EMB, out, 0);

    add_bias<<<(BATCH * SEQ * EMB + 511) / 512, 512>>>(out, bo);
}

// round 4
// speedup vs baseline: 1.7813x; 1.0303x over previous
#include <cuda_runtime.h>
#include <cstdint>
#include <mma.h>

using namespace nvcuda;

// ---------------- problem constants ----------------
#define BATCH 4
#define SEQ 2048
#define EMB 2048
#define NH 16
#define DH 128
#define BH (BATCH * NH)          // 64
#define SD (SEQ * DH)            // 262144
#define SS ((size_t)SEQ * SEQ)

// scratch (allocation-free rule)
__device__ float g_q[(size_t)BH * SD];
__device__ float g_k[(size_t)BH * SD];
__device__ float g_v[(size_t)BH * SD];
__device__ float g_scores[(size_t)BH * SS];
__device__ float g_ctx[(size_t)BATCH * SEQ * EMB];
__device__ float g_xt[(size_t)BATCH * SEQ * EMB];   // tf32-rounded x
__device__ float g_wt[4][(size_t)EMB * EMB];        // tf32-rounded Wq,Wk,Wv,Wo

__device__ __forceinline__ float rtf32(float x) {
    float y;
    asm("cvt.rna.tf32.f32 %0, %1;" : "=f"(y) : "f"(x));
    return y;
}
__device__ __forceinline__ uint32_t smem_u32(const void* p) {
    return (uint32_t)__cvta_generic_to_shared(p);
}
__device__ __forceinline__ void cp16(uint32_t s, const void* g) {
    asm volatile("cp.async.cg.shared.global [%0], [%1], 16;\n" :: "r"(s), "l"(g));
}

// ---------------------------------------------------------------------------
// TF32 WMMA GEMM, CTA tile 256x128, warp tile 64x64 (8 warps = 4 row x 2 col),
// BK=32, 3-stage cp.async pipeline, no conversions in mainloop.
// MODE 0: QKV proj   C = x_t * W_t^T, scatter to g_q/g_k/g_v per head (rounded)
// MODE 1: scores     C = Q K^T per (b,h); fully-masked blocks skipped
// MODE 2: ctx        C = P V per (b,h); K truncated causally (rounded store)
// MODE 3: out proj   C = ctx * Wo_t^T
// ---------------------------------------------------------------------------
#define BM 256
#define BK 32
#define A_STRIDE 40
#define B_STRIDE 40
#define B2_STRIDE 136
#define A_BYTES (BM * A_STRIDE * 4)                 // 40960
#define STAGE_BYTES (A_BYTES + 128 * B_STRIDE * 4)  // 61440
#define NSTAGE 3
#define SMEM_BYTES (NSTAGE * STAGE_BYTES)           // 184320

template<int MODE>
__global__ __launch_bounds__(256)
void gemm_tc(const float* __restrict__ Aext, const float* __restrict__ Bext,
             float* __restrict__ Oext, int sel)
{
    if (MODE == 1 && blockIdx.x > 2 * blockIdx.y + 1) return;  // fully-masked causal block

    extern __shared__ float dyn[];

    const int tid = threadIdx.x;
    const int wid = tid >> 5;
    const int wr  = wid & 3;    // 4 row groups of 64
    const int wc  = wid >> 2;   // 2 col groups of 64
    const int m0  = blockIdx.y * BM;
    const int n0  = blockIdx.x * 128;
    const int z   = blockIdx.z;

    const float* A;  int lda;
    const float* Bm; int ldb;
    int Ktot;
    if (MODE == 0)      { A = Aext;                      lda = EMB; Bm = Bext;                 ldb = EMB; Ktot = EMB; }
    else if (MODE == 1) { A = g_q + (size_t)z * SD;      lda = DH;  Bm = g_k + (size_t)z * SD; ldb = DH;  Ktot = DH; }
    else if (MODE == 2) { A = g_scores + (size_t)z * SS; lda = SEQ; Bm = g_v + (size_t)z * SD; ldb = DH;  Ktot = m0 + BM; }
    else                { A = g_ctx;                     lda = EMB; Bm = Bext;                 ldb = EMB; Ktot = EMB; }
    const int T = Ktot / BK;

    const uint32_t sbase = smem_u32(dyn);

    auto load_stage = [&](int buf, int t) {
        const uint32_t sa = sbase + (uint32_t)buf * STAGE_BYTES;
        const uint32_t sb = sa + A_BYTES;
        const int k0 = t * BK;
        // A: 256 x 32, row stride 40 floats  (2048 float4 chunks, 8 per thread)
        #pragma unroll
        for (int i = 0; i < 8; i++) {
            int id = tid + i * 256;
            int r = id >> 3, c = (id & 7) * 4;
            cp16(sa + (uint32_t)(r * A_STRIDE + c) * 4,
                 A + (size_t)(m0 + r) * lda + k0 + c);
        }
        if (MODE != 2) {
            // B rows are N-dim, K contiguous: 128 x 32, stride 40
            #pragma unroll
            for (int i = 0; i < 4; i++) {
                int id = tid + i * 256;
                int r = id >> 3, c = (id & 7) * 4;
                cp16(sb + (uint32_t)(r * B_STRIDE + c) * 4,
                     Bm + (size_t)(n0 + r) * ldb + k0 + c);
            }
        } else {
            // V row-major [K, 128]: Bs[k][n], 32 x 128, stride 136
            #pragma unroll
            for (int i = 0; i < 4; i++) {
                int id = tid + i * 256;
                int r = id >> 5, c = (id & 31) * 4;
                cp16(sb + (uint32_t)(r * B2_STRIDE + c) * 4,
                     Bm + (size_t)(k0 + r) * ldb + n0 + c);
            }
        }
        asm volatile("cp.async.commit_group;\n");
    };

    wmma::fragment<wmma::accumulator, 16, 16, 8, float> acc[4][4];
    #pragma unroll
    for (int i = 0; i < 4; i++)
        #pragma unroll
        for (int j = 0; j < 4; j++)
            wmma::fill_fragment(acc[i][j], 0.0f);

    load_stage(0, 0);
    load_stage(1, 1);

    for (int t = 0; t < T; t++) {
        asm volatile("cp.async.wait_group 1;\n" ::: "memory");
        __syncthreads();

        if (t + 2 < T) load_stage((t + 2) % NSTAGE, t + 2);
        else asm volatile("cp.async.commit_group;\n");

        const float* As = dyn + ((t % NSTAGE) * STAGE_BYTES) / 4;
        const float* Bs = As + A_BYTES / 4;

        #pragma unroll
        for (int ks = 0; ks < 4; ks++) {
            wmma::fragment<wmma::matrix_a, 16, 16, 8, wmma::precision::tf32, wmma::row_major> af[4];
            #pragma unroll
            for (int i = 0; i < 4; i++)
                wmma::load_matrix_sync(af[i], &As[(wr * 64 + i * 16) * A_STRIDE + ks * 8], A_STRIDE);
            if (MODE != 2) {
                #pragma unroll
                for (int j = 0; j < 4; j++) {
                    wmma::fragment<wmma::matrix_b, 16, 16, 8, wmma::precision::tf32, wmma::col_major> bf;
                    wmma::load_matrix_sync(bf, &Bs[(wc * 64 + j * 16) * B_STRIDE + ks * 8], B_STRIDE);
                    #pragma unroll
                    for (int i = 0; i < 4; i++)
                        wmma::mma_sync(acc[i][j], af[i], bf, acc[i][j]);
                }
            } else {
                #pragma unroll
                for (int j = 0; j < 4; j++) {
                    wmma::fragment<wmma::matrix_b, 16, 16, 8, wmma::precision::tf32, wmma::row_major> bf;
                    wmma::load_matrix_sync(bf, &Bs[(ks * 8) * B2_STRIDE + wc * 64 + j * 16], B2_STRIDE);
                    #pragma unroll
                    for (int i = 0; i < 4; i++)
                        wmma::mma_sync(acc[i][j], af[i], bf, acc[i][j]);
                }
            }
        }
    }

    // ---- epilogue ----
    float* outp; int ldo;
    bool do_round;
    if (MODE == 0) {
        int b = m0 >> 11;
        float* qkv = (sel == 0 ? g_q : sel == 1 ? g_k : g_v);
        outp = qkv + ((size_t)(b * NH + blockIdx.x)) * SD + (size_t)(m0 & (SEQ - 1)) * DH;
        ldo = DH;
        do_round = true;
    } else if (MODE == 1) {
        outp = g_scores + (size_t)z * SS + (size_t)m0 * SEQ + n0;
        ldo = SEQ;
        do_round = false;
    } else if (MODE == 2) {
        int b = z >> 4, h = z & 15;
        outp = g_ctx + (size_t)b * SEQ * EMB + (size_t)m0 * EMB + h * DH;
        ldo = EMB;
        do_round = true;
    } else {
        outp = Oext + (size_t)m0 * EMB + n0;
        ldo = EMB;
        do_round = false;
    }

    #pragma unroll
    for (int i = 0; i < 4; i++)
        #pragma unroll
        for (int j = 0; j < 4; j++) {
            if (do_round) {
                #pragma unroll
                for (int e = 0; e < acc[i][j].num_elements; e++)
                    acc[i][j].x[e] = rtf32(acc[i][j].x[e]);
            }
            wmma::store_matrix_sync(outp + (size_t)(wr * 64 + i * 16) * ldo + wc * 64 + j * 16,
                                    acc[i][j], ldo, wmma::mem_row_major);
        }
}

// ---------------------------------------------------------------------------
// causal row softmax, in place; zero-fill only to the 256-aligned frontier
// (MODE2's truncated K loop never reads beyond it)
// ---------------------------------------------------------------------------
__global__ __launch_bounds__(256)
void softmax_causal()
{
    const int q  = blockIdx.x;
    const int bh = blockIdx.y;
    float* row = g_scores + (size_t)bh * SS + (size_t)q * SEQ;
    const float inv = 0.08838834764831845f;   // 1/sqrt(128)
    const int n = q + 1;
    const int lim = ((q >> 8) + 1) << 8;      // 256-aligned frontier
    const int t = threadIdx.x;

    float vals[8];
    float m = -1e30f;
    #pragma unroll
    for (int i = 0; i < 8; i++) {
        int idx = t + i * 256;
        float v = (idx < n) ? row[idx] : -1e30f;
        vals[i] = v;
        m = fmaxf(m, v);
    }
    __shared__ float red[256];
    red[t] = m; __syncthreads();
    #pragma unroll
    for (int s = 128; s > 0; s >>= 1) {
        if (t < s) red[t] = fmaxf(red[t], red[t + s]);
        __syncthreads();
    }
    m = red[0];
    __syncthreads();

    float sum = 0.0f;
    #pragma unroll
    for (int i = 0; i < 8; i++) {
        int idx = t + i * 256;
        if (idx < n) {
            float p = __expf((vals[i] - m) * inv);
            vals[i] = p;
            sum += p;
        }
    }
    red[t] = sum; __syncthreads();
    #pragma unroll
    for (int s = 128; s > 0; s >>= 1) {
        if (t < s) red[t] += red[t + s];
        __syncthreads();
    }
    const float rs = 1.0f / red[0];

    #pragma unroll
    for (int i = 0; i < 8; i++) {
        int idx = t + i * 256;
        if (idx < lim) row[idx] = (idx < n) ? rtf32(vals[i] * rs) : 0.0f;
    }
}

// elementwise tf32 rounding pre-pass (float4)
__global__ void round_pass(const float4* __restrict__ in, float4* __restrict__ out, int n4)
{
    int i = blockIdx.x * blockDim.x + threadIdx.x;
    if (i < n4) {
        float4 v = in[i];
        v.x = rtf32(v.x); v.y = rtf32(v.y); v.z = rtf32(v.z); v.w = rtf32(v.w);
        out[i] = v;
    }
}

__global__ void add_bias(float* __restrict__ out, const float* __restrict__ bo)
{
    size_t i = (size_t)blockIdx.x * blockDim.x + threadIdx.x;
    if (i < (size_t)BATCH * SEQ * EMB) out[i] += bo[i & (EMB - 1)];
}

extern "C" void kernel_launch(void* const* d_in, const int* in_sizes, int n_in,
                              void* d_out, int out_size)
{
    const float* x  = (const float*)d_in[0];
    const float* W[4] = {(const float*)d_in[1], (const float*)d_in[2],
                         (const float*)d_in[3], (const float*)d_in[4]};
    const float* bo = (const float*)d_in[5];
    float* out = (float*)d_out;

    cudaFuncSetAttribute(gemm_tc<0>, cudaFuncAttributeMaxDynamicSharedMemorySize, SMEM_BYTES);
    cudaFuncSetAttribute(gemm_tc<1>, cudaFuncAttributeMaxDynamicSharedMemorySize, SMEM_BYTES);
    cudaFuncSetAttribute(gemm_tc<2>, cudaFuncAttributeMaxDynamicSharedMemorySize, SMEM_BYTES);
    cudaFuncSetAttribute(gemm_tc<3>, cudaFuncAttributeMaxDynamicSharedMemorySize, SMEM_BYTES);

    float *xt, *wt;
    cudaGetSymbolAddress((void**)&xt, g_xt);
    cudaGetSymbolAddress((void**)&wt, g_wt);

    dim3 blk(256);
    const int XN4 = BATCH * SEQ * EMB / 4;
    const int WN4 = EMB * EMB / 4;

    round_pass<<<(XN4 + 255) / 256, 256>>>((const float4*)x, (float4*)xt, XN4);
    for (int i = 0; i < 4; i++)
        round_pass<<<(WN4 + 255) / 256, 256>>>((const float4*)W[i],
                                               (float4*)(wt + (size_t)i * EMB * EMB), WN4);

    // QKV projections: M=8192 (32 tiles of 256), N=2048 (16 tiles = heads)
    gemm_tc<0><<<dim3(16, 32, 1), blk, SMEM_BYTES>>>(xt, wt + 0 * (size_t)EMB * EMB, nullptr, 0);
    gemm_tc<0><<<dim3(16, 32, 1), blk, SMEM_BYTES>>>(xt, wt + 1 * (size_t)EMB * EMB, nullptr, 1);
    gemm_tc<0><<<dim3(16, 32, 1), blk, SMEM_BYTES>>>(xt, wt + 2 * (size_t)EMB * EMB, nullptr, 2);

    // scores = Q K^T per (b,h); 256-row tiles, fully-masked blocks skipped
    gemm_tc<1><<<dim3(16, 8, BH), blk, SMEM_BYTES>>>(nullptr, nullptr, nullptr, 0);

    // causal softmax (scale folded in), in place
    softmax_causal<<<dim3(SEQ, BH), blk>>>();

    // ctx = P V per (b,h); K truncated causally
    gemm_tc<2><<<dim3(1, 8, BH), blk, SMEM_BYTES>>>(nullptr, nullptr, nullptr, 0);

    // out = ctx Wo^T
    gemm_tc<3><<<dim3(16, 32, 1), blk, SMEM_BYTES>>>(nullptr, wt + 3 * (size_t)EMB * EMB, out, 0);

    add_bias<<<(BATCH * SEQ * EMB + 511) / 512, 512>>>(out, bo);
}